// round 1
// baseline (speedup 1.0000x reference)
#include <cuda_runtime.h>

// BilinearResNet fused kernel for GB300 (sm_103a)
// x[B,784] -> h_x = x @ We^T [B,16] -> 4 bilinear residual blocks -> logits [B,10]
// Outputs (in d_out, fp32): logits [B,10], then h_i [B,6] for i=0..3.

#define IN_DIM   784
#define DM       16
#define HID      6
#define NB       4
#define NC       10
#define KC       112      // K-chunk (784 = 7*112 exactly)
#define NCHUNK   7
#define ROWS     128      // rows per block
#define NTHREADS 256
#define XPAD     116      // padded floats per row in Xs (16B aligned, conflict-ok)

// shared memory layout (float offsets)
#define XS0   0                       // 2 * ROWS * XPAD = 29696
#define XSBUF (ROWS*XPAD)             // 14848
#define WS    29696                   // W_embed [16][784] = 12544
#define LW    42240                   // L_w 4*6*16 = 384
#define RW    42624                   // R_w 384
#define DT    43008                   // D_w transposed [i][a][16] = 384
#define WH    43392                   // W_head 10*16 = 160
#define HXS   43552                   // hx tile [128][17] = 2176
#define SMEM_FLOATS 45728             // 182,912 bytes

__device__ __forceinline__ void cp_async16(unsigned dst, const void* src) {
    asm volatile("cp.async.cg.shared.global [%0], [%1], 16;\n" :: "r"(dst), "l"(src));
}

__global__ __launch_bounds__(NTHREADS, 1)
void bilinear_resnet_kernel(const float* __restrict__ x,
                            const float* __restrict__ We,
                            const float* __restrict__ Lw,
                            const float* __restrict__ Rw,
                            const float* __restrict__ Dw,
                            const float* __restrict__ Wh,
                            float* __restrict__ out,
                            int batch)
{
    extern __shared__ float sm[];
    const int tid = threadIdx.x;

    // ---- stage W_embed (layout identical: [j][k]) ----
    {
        float4* d = (float4*)(sm + WS);
        const float4* s = (const float4*)We;
        #pragma unroll 2
        for (int i = tid; i < (DM*IN_DIM)/4; i += NTHREADS) d[i] = s[i];
    }
    // ---- stage small weights ----
    for (int i = tid; i < NB*HID*DM; i += NTHREADS) { sm[LW+i] = Lw[i]; sm[RW+i] = Rw[i]; }
    for (int idx = tid; idx < NB*DM*HID; idx += NTHREADS) {
        int i = idx / (DM*HID); int r = idx % (DM*HID);
        int j = r / HID; int a = r % HID;
        sm[DT + i*(DM*HID) + a*DM + j] = Dw[idx];     // transpose to [i][a][j]
    }
    for (int i = tid; i < NC*DM; i += NTHREADS) sm[WH+i] = Wh[i];

    const long long row0 = (long long)blockIdx.x * ROWS;
    const unsigned smbase = (unsigned)__cvta_generic_to_shared(sm);

    // stage one K-chunk of x into Xs[buf] with cp.async (14 x 16B per thread)
    auto stage = [&](int c, int buf) {
        const float* xc = x + row0*IN_DIM + c*KC;
        #pragma unroll
        for (int i = 0; i < (ROWS*KC/4)/NTHREADS; i++) {   // 14 iters
            int f   = tid + i*NTHREADS;
            int row = f / (KC/4);          // /28
            int kq  = f % (KC/4);
            unsigned dst = smbase + (unsigned)((XS0 + buf*XSBUF + row*XPAD + kq*4) * 4);
            cp_async16(dst, xc + (long long)row*IN_DIM + kq*4);
        }
        asm volatile("cp.async.commit_group;\n");
    };

    stage(0, 0);

    const int warp = tid >> 5, lane = tid & 31;
    const int myrow = (warp & 3)*32 + lane;    // 0..127
    const int j0    = (warp >> 2)*8;           // 0 or 8

    float acc[8] = {0.f,0.f,0.f,0.f,0.f,0.f,0.f,0.f};

    for (int c = 0; c < NCHUNK; c++) {
        if (c + 1 < NCHUNK) stage(c + 1, (c + 1) & 1);
        if (c < NCHUNK - 1) asm volatile("cp.async.wait_group 1;\n");
        else                asm volatile("cp.async.wait_group 0;\n");
        __syncthreads();

        const float* xr = sm + XS0 + (c & 1)*XSBUF + myrow*XPAD;
        const float* wb = sm + WS + c*KC;
        #pragma unroll 4
        for (int kq = 0; kq < KC/4; kq++) {
            float4 xv = *(const float4*)(xr + kq*4);
            #pragma unroll
            for (int j = 0; j < 8; j++) {
                float4 w = *(const float4*)(wb + (j0 + j)*IN_DIM + kq*4);
                acc[j] = fmaf(xv.x, w.x,
                         fmaf(xv.y, w.y,
                         fmaf(xv.z, w.z,
                         fmaf(xv.w, w.w, acc[j]))));
            }
        }
        __syncthreads();
    }

    // ---- gather h_x per row into smem ----
    #pragma unroll
    for (int j = 0; j < 8; j++) sm[HXS + myrow*17 + j0 + j] = acc[j];
    __syncthreads();

    // ---- phase 2: bilinear blocks + head, one thread per row ----
    if (tid < ROWS) {
        float hx[DM];
        #pragma unroll
        for (int j = 0; j < DM; j++) hx[j] = sm[HXS + tid*17 + j];

        const long long grow = row0 + tid;
        const long long hbase = (long long)batch * NC;
        const long long hblk  = (long long)batch * HID;

        #pragma unroll
        for (int ib = 0; ib < NB; ib++) {
            float h[HID];
            #pragma unroll
            for (int a = 0; a < HID; a++) {
                const float4* lp = (const float4*)(sm + LW + ib*(HID*DM) + a*DM);
                const float4* rp = (const float4*)(sm + RW + ib*(HID*DM) + a*DM);
                float su = 0.f, sv = 0.f;
                #pragma unroll
                for (int q = 0; q < 4; q++) {
                    float4 l4 = lp[q], r4 = rp[q];
                    su = fmaf(l4.x, hx[q*4+0], fmaf(l4.y, hx[q*4+1],
                         fmaf(l4.z, hx[q*4+2], fmaf(l4.w, hx[q*4+3], su))));
                    sv = fmaf(r4.x, hx[q*4+0], fmaf(r4.y, hx[q*4+1],
                         fmaf(r4.z, hx[q*4+2], fmaf(r4.w, hx[q*4+3], sv))));
                }
                h[a] = su * sv;
            }
            #pragma unroll
            for (int a = 0; a < HID; a++)
                out[hbase + (long long)ib*hblk + grow*HID + a] = h[a];
            #pragma unroll
            for (int a = 0; a < HID; a++) {
                const float4* dp = (const float4*)(sm + DT + ib*(DM*HID) + a*DM);
                #pragma unroll
                for (int q = 0; q < 4; q++) {
                    float4 d4 = dp[q];
                    hx[q*4+0] = fmaf(h[a], d4.x, hx[q*4+0]);
                    hx[q*4+1] = fmaf(h[a], d4.y, hx[q*4+1]);
                    hx[q*4+2] = fmaf(h[a], d4.z, hx[q*4+2]);
                    hx[q*4+3] = fmaf(h[a], d4.w, hx[q*4+3]);
                }
            }
        }

        #pragma unroll
        for (int cc = 0; cc < NC; cc++) {
            const float4* wp = (const float4*)(sm + WH + cc*DM);
            float s = 0.f;
            #pragma unroll
            for (int q = 0; q < 4; q++) {
                float4 w4 = wp[q];
                s = fmaf(w4.x, hx[q*4+0], fmaf(w4.y, hx[q*4+1],
                    fmaf(w4.z, hx[q*4+2], fmaf(w4.w, hx[q*4+3], s))));
            }
            out[grow*NC + cc] = s;
        }
    }
}

extern "C" void kernel_launch(void* const* d_in, const int* in_sizes, int n_in,
                              void* d_out, int out_size)
{
    const float* x  = (const float*)d_in[0];
    const float* We = (const float*)d_in[1];
    const float* Lw = (const float*)d_in[2];
    const float* Rw = (const float*)d_in[3];
    const float* Dw = (const float*)d_in[4];
    const float* Wh = (const float*)d_in[5];
    float* out = (float*)d_out;

    int batch = in_sizes[0] / IN_DIM;          // 65536
    int grid  = batch / ROWS;                  // 512
    size_t smem = (size_t)SMEM_FLOATS * sizeof(float);   // ~183 KB

    cudaFuncSetAttribute(bilinear_resnet_kernel,
                         cudaFuncAttributeMaxDynamicSharedMemorySize, (int)smem);
    bilinear_resnet_kernel<<<grid, NTHREADS, smem>>>(x, We, Lw, Rw, Dw, Wh, out, batch);
}